// round 7
// baseline (speedup 1.0000x reference)
#include <cuda_runtime.h>
#include <math.h>
#include <float.h>
#include <stdint.h>

// Problem constants
#define H_   248
#define W_   216
#define HW   (H_*W_)          // 53568
#define NANCH 6
#define NTOT (HW*NANCH)       // 321408 rows per batch
#define BSZ  16
#define NPRE 100
#define MAXN 50
#define NBINS 2048
#define CAP   3072

// Scratch (static device allocations are allowed)
__device__ float g_score[BSZ][NTOT];   // max logit per row, layout j = a*HW + s
__device__ int   g_hist[BSZ][NBINS];
__device__ int   g_top[BSZ][NPRE];     // original row index i = s*6 + a, descending score order

__device__ __forceinline__ unsigned fkey(float v) {
    unsigned b = __float_as_uint(v);
    return (b & 0x80000000u) ? ~b : (b | 0x80000000u); // monotone float->uint
}

// ---------------------------------------------------------------------------
__global__ void k_zero_hist() {
    int i = blockIdx.x * blockDim.x + threadIdx.x;
    if (i < BSZ * NBINS) ((int*)g_hist)[i] = 0;
}

// Pass 1: max-logit per anchor row + per-batch histogram of key top-11 bits
__global__ void k_score(const float* __restrict__ cls) {
    __shared__ int sh[NBINS];
    for (int i = threadIdx.x; i < NBINS; i += blockDim.x) sh[i] = 0;
    __syncthreads();

    int b = blockIdx.y;
    int j = blockIdx.x * blockDim.x + threadIdx.x; // j = a*HW + s
    if (j < NTOT) {
        int a = j / HW, s = j - a * HW;
        const float* base = cls + (size_t)b * 18 * HW + (size_t)(3 * a) * HW + s;
        float v0 = base[0];
        float v1 = base[HW];
        float v2 = base[2 * HW];
        float m = fmaxf(v0, fmaxf(v1, v2));
        g_score[b][j] = m;
        atomicAdd(&sh[fkey(m) >> 21], 1);
    }
    __syncthreads();
    for (int i = threadIdx.x; i < NBINS; i += blockDim.x)
        if (sh[i]) atomicAdd(&g_hist[b][i], sh[i]);
}

// Pass 2: per batch — threshold bin from histogram, collect candidates,
// exact ordered top-100 by (value desc, index asc)  [matches lax.top_k]
__global__ void k_select() {
    int b   = blockIdx.x;
    int tid = threadIdx.x;

    __shared__ float cv[CAP];
    __shared__ int   ci[CAP];
    __shared__ float rv[1024];
    __shared__ int   ri[1024];
    __shared__ int   rs[1024];
    __shared__ int   s_t, s_c;

    if (tid == 0) {
        int acc = 0, t = 0;
        for (int k = NBINS - 1; k >= 0; k--) {
            acc += g_hist[b][k];
            if (acc >= NPRE) { t = k; break; }
        }
        s_t = t;
        s_c = 0;
    }
    __syncthreads();
    unsigned t = (unsigned)s_t;

    for (int j = tid; j < NTOT; j += blockDim.x) {
        float v = g_score[b][j];
        if ((fkey(v) >> 21) >= t) {
            int slot = atomicAdd(&s_c, 1);
            if (slot < CAP) {
                cv[slot] = v;
                int a = j / HW, s = j - a * HW;
                ci[slot] = s * 6 + a; // original reshaped row index
            }
        }
    }
    __syncthreads();
    int C = min(s_c, CAP); // >= 100 by construction

    for (int k = 0; k < NPRE; k++) {
        float bv = -FLT_MAX; int bi = 0x7fffffff, bsl = -1;
        for (int u = tid; u < C; u += blockDim.x) {
            float v = cv[u]; int idx = ci[u];
            if (v > bv || (v == bv && idx < bi)) { bv = v; bi = idx; bsl = u; }
        }
        rv[tid] = bv; ri[tid] = bi; rs[tid] = bsl;
        __syncthreads();
        for (int off = blockDim.x / 2; off > 0; off >>= 1) {
            if (tid < off) {
                float v2 = rv[tid + off]; int i2 = ri[tid + off];
                if (v2 > rv[tid] || (v2 == rv[tid] && i2 < ri[tid])) {
                    rv[tid] = v2; ri[tid] = i2; rs[tid] = rs[tid + off];
                }
            }
            __syncthreads();
        }
        if (tid == 0) {
            g_top[b][k] = ri[0];
            if (rs[0] >= 0) cv[rs[0]] = -FLT_MAX; // consume winner
        }
        __syncthreads();
    }
}

// Pass 3: per batch — gather/decode 100 boxes, per-class NMS (3 warps),
// final ordered top-50, write outputs.
__global__ void k_final(const float* __restrict__ cls,
                        const float* __restrict__ box,
                        const float* __restrict__ dir,
                        const float* __restrict__ anc,
                        float* __restrict__ out) {
    int b   = blockIdx.x;
    int tid = threadIdx.x;

    __shared__ float bb[NPRE][7];
    __shared__ float b2d[NPRE][4];
    __shared__ float area[NPRE];
    __shared__ float sc3[3][NPRE];
    __shared__ float kv[3][NPRE];
    __shared__ int   ordc[3][NPRE];
    __shared__ int   keepS[3][NPRE];   // sorted-order keep flags
    __shared__ int   keepP[3][NPRE];   // position-order keep flags
    __shared__ float fv[3 * NPRE];

    const float PI = 3.14159265358979323846f;

    if (tid < NPRE) {
        int i = g_top[b][tid];
        int s = i / 6, a = i - 6 * s;

        const float* cb = cls + (size_t)b * 18 * HW + s;
        #pragma unroll
        for (int c = 0; c < 3; c++) {
            float x = cb[(size_t)(3 * a + c) * HW];
            sc3[c][tid] = 0.5f * tanhf(0.5f * x) + 0.5f; // sigmoid, XLA-style
        }

        const float* pb = box + (size_t)b * 42 * HW + s;
        float d[7];
        #pragma unroll
        for (int j = 0; j < 7; j++) d[j] = pb[(size_t)(7 * a + j) * HW];

        const float* db = dir + (size_t)b * 12 * HW + s;
        float d0 = db[(size_t)(2 * a) * HW];
        float d1 = db[(size_t)(2 * a + 1) * HW];
        int dircls = (d1 > d0) ? 1 : 0; // argmax, ties -> 0

        const float* ab = anc + (size_t)i * 7;
        float xa = ab[0], ya = ab[1], za = ab[2];
        float wa = ab[3], la = ab[4], ha = ab[5], ra = ab[6];

        float da = sqrtf(wa * wa + la * la);
        float x = d[0] * da + xa;
        float y = d[1] * da + ya;
        float z = d[2] * ha + za + ha * 0.5f;
        float w = wa * expf(d[3]);
        float l = la * expf(d[4]);
        float h = ha * expf(d[5]);
        z = z - h * 0.5f;
        float th0 = ra + d[6];
        float lp  = th0 - floorf(th0 / PI + 1.0f) * PI;
        float th  = lp + (1.0f - (float)dircls) * PI;

        bb[tid][0] = x; bb[tid][1] = y; bb[tid][2] = z;
        bb[tid][3] = w; bb[tid][4] = l; bb[tid][5] = h; bb[tid][6] = th;

        float x1 = x - w * 0.5f, y1 = y - l * 0.5f;
        float x2 = x + w * 0.5f, y2 = y + l * 0.5f;
        b2d[tid][0] = x1; b2d[tid][1] = y1; b2d[tid][2] = x2; b2d[tid][3] = y2;
        area[tid] = (x2 - x1) * (y2 - y1);
    }
    __syncthreads();

    int wp = tid >> 5, lane = tid & 31;
    if (wp < 3) {
        int c = wp;
        // keys: valid ? score : -inf  (stable argsort desc == (v desc, idx asc))
        for (int tt = lane; tt < NPRE; tt += 32) {
            float s = sc3[c][tt];
            kv[c][tt] = (s > 0.1f) ? s : -FLT_MAX;
        }
        __syncwarp();
        for (int tt = lane; tt < NPRE; tt += 32) {
            float v = kv[c][tt];
            int r = 0;
            #pragma unroll 4
            for (int u = 0; u < NPRE; u++) {
                float vu = kv[c][u];
                r += (vu > v) || (vu == v && u < tt);
            }
            ordc[c][r] = tt;
        }
        __syncwarp();
        for (int rr = lane; rr < NPRE; rr += 32)
            keepS[c][rr] = (kv[c][ordc[c][rr]] != -FLT_MAX) ? 1 : 0;
        __syncwarp();

        // greedy NMS (IoU > 0.01), suppression only from still-kept boxes
        for (int ii = 0; ii < NPRE - 1; ii++) {
            if (keepS[c][ii]) {
                int bi = ordc[c][ii];
                float ax1 = b2d[bi][0], ay1 = b2d[bi][1];
                float ax2 = b2d[bi][2], ay2 = b2d[bi][3];
                float aa  = area[bi];
                for (int jj = ii + 1 + lane; jj < NPRE; jj += 32) {
                    if (!keepS[c][jj]) continue;
                    int bj = ordc[c][jj];
                    float x1 = fmaxf(ax1, b2d[bj][0]);
                    float y1 = fmaxf(ay1, b2d[bj][1]);
                    float x2 = fminf(ax2, b2d[bj][2]);
                    float y2 = fminf(ay2, b2d[bj][3]);
                    float inter = fmaxf(x2 - x1, 0.0f) * fmaxf(y2 - y1, 0.0f);
                    float iou = inter / (aa + area[bj] - inter + 1e-8f);
                    if (iou > 0.01f) keepS[c][jj] = 0;
                }
            }
            __syncwarp();
        }

        for (int rr = lane; rr < NPRE; rr += 32)
            keepP[c][ordc[c][rr]] = keepS[c][rr];
        __syncwarp();
        for (int p = lane; p < NPRE; p += 32)
            fv[c * NPRE + p] = keepP[c][p] ? sc3[c][p] : -1.0f;
    }
    __syncthreads();

    // top-50 over 300 flat entries, (value desc, flat index asc) — exact top_k
    for (int e = tid; e < 3 * NPRE; e += blockDim.x) {
        float v = fv[e];
        int r = 0;
        for (int u = 0; u < 3 * NPRE; u++) {
            float vu = fv[u];
            r += (vu > v) || (vu == v && u < e);
        }
        if (r < MAXN) {
            int sel = e % NPRE;
            int lab = e / NPRE;
            // output layout: bboxes[16*50*7] | labels[800] | scores[800] | mask[800]
            float* ob = out + (size_t)b * MAXN * 7 + (size_t)r * 7;
            #pragma unroll
            for (int j = 0; j < 7; j++) ob[j] = bb[sel][j];
            out[BSZ * MAXN * 7 +                 b * MAXN + r] = (float)lab;
            out[BSZ * MAXN * 7 + BSZ * MAXN +    b * MAXN + r] = v;
            out[BSZ * MAXN * 7 + 2 * BSZ * MAXN + b * MAXN + r] = (v > 0.0f) ? 1.0f : 0.0f;
        }
    }
}

// ---------------------------------------------------------------------------
extern "C" void kernel_launch(void* const* d_in, const int* in_sizes, int n_in,
                              void* d_out, int out_size) {
    const float* cls = (const float*)d_in[0]; // (16,18,248,216)
    const float* box = (const float*)d_in[1]; // (16,42,248,216)
    const float* dir = (const float*)d_in[2]; // (16,12,248,216)
    const float* anc = (const float*)d_in[3]; // (248,216,3,2,7)
    float* out = (float*)d_out;

    k_zero_hist<<<(BSZ * NBINS + 255) / 256, 256>>>();

    dim3 g1((NTOT + 255) / 256, BSZ);
    k_score<<<g1, 256>>>(cls);

    k_select<<<BSZ, 1024>>>();

    k_final<<<BSZ, 128>>>(cls, box, dir, anc, out);
}

// round 8
// speedup vs baseline: 5.1979x; 5.1979x over previous
#include <cuda_runtime.h>
#include <math.h>
#include <float.h>
#include <stdint.h>

// Problem constants
#define H_   248
#define W_   216
#define HW   (H_*W_)          // 53568
#define NANCH 6
#define NTOT (HW*NANCH)       // 321408 rows per batch
#define NT4  (NTOT/4)         // 80352
#define BSZ  16
#define NPRE 100
#define MAXN 50
#define NBINS 2048
#define CAP   3072

// Scratch (static device allocations are allowed)
__device__ float g_score[BSZ][NTOT];            // max logit per row, layout j = a*HW + s
__device__ int   g_hist[BSZ][NBINS];
__device__ int   g_thr[BSZ];
__device__ int   g_cnt[BSZ];
__device__ unsigned long long g_ck[BSZ][CAP];   // packed (fkey(v)<<32)|(~i)
__device__ float g_bbx[BSZ][NPRE][7];
__device__ float g_b2dx[BSZ][NPRE][4];
__device__ float g_areax[BSZ][NPRE];
__device__ float g_sc3x[BSZ][3][NPRE];
__device__ float g_fv[BSZ][3*NPRE];

__device__ __forceinline__ unsigned fkey(float v) {
    unsigned b = __float_as_uint(v);
    return (b & 0x80000000u) ? ~b : (b | 0x80000000u); // monotone float->uint
}

// ---------------------------------------------------------------------------
__global__ void k_zero() {
    int i = blockIdx.x * blockDim.x + threadIdx.x;
    if (i < BSZ * NBINS) ((int*)g_hist)[i] = 0;
    if (i < BSZ) g_cnt[i] = 0;
}

// Pass 1: max-logit per anchor row (float4) + per-batch histogram (11-bit key)
__global__ void k_score(const float* __restrict__ cls) {
    __shared__ int sh[NBINS];
    for (int i = threadIdx.x; i < NBINS; i += blockDim.x) sh[i] = 0;
    __syncthreads();

    int b = blockIdx.y;
    int j4 = blockIdx.x * blockDim.x + threadIdx.x;
    if (j4 < NT4) {
        int j = j4 * 4;
        int a = j / HW, s = j - a * HW;       // 4-group never crosses 'a' (HW%4==0)
        const float4* base = (const float4*)(cls + (size_t)b * 18 * HW + (size_t)(3 * a) * HW + s);
        float4 v0 = base[0];
        float4 v1 = base[HW / 4];
        float4 v2 = base[2 * (HW / 4)];
        float4 m;
        m.x = fmaxf(v0.x, fmaxf(v1.x, v2.x));
        m.y = fmaxf(v0.y, fmaxf(v1.y, v2.y));
        m.z = fmaxf(v0.z, fmaxf(v1.z, v2.z));
        m.w = fmaxf(v0.w, fmaxf(v1.w, v2.w));
        ((float4*)g_score[b])[j4] = m;
        atomicAdd(&sh[fkey(m.x) >> 21], 1);
        atomicAdd(&sh[fkey(m.y) >> 21], 1);
        atomicAdd(&sh[fkey(m.z) >> 21], 1);
        atomicAdd(&sh[fkey(m.w) >> 21], 1);
    }
    __syncthreads();
    for (int i = threadIdx.x; i < NBINS; i += blockDim.x)
        if (sh[i]) atomicAdd(&g_hist[b][i], sh[i]);
}

// Threshold bin per batch: largest t with sum_{k>=t} hist[k] >= NPRE
__global__ void k_thresh() {
    int b = blockIdx.x, tid = threadIdx.x;  // 256 threads
    __shared__ int a[256];
    __shared__ int red[256];
    int binv[8];
    int base = tid * 8, s = 0;
    #pragma unroll
    for (int k = 0; k < 8; k++) { binv[k] = g_hist[b][base + k]; s += binv[k]; }
    a[tid] = s;
    __syncthreads();
    // inclusive suffix sum over 256 chunk sums
    for (int off = 1; off < 256; off <<= 1) {
        int t = (tid + off < 256) ? a[tid + off] : 0;
        __syncthreads();
        a[tid] += t;
        __syncthreads();
    }
    int acc = (tid < 255) ? a[tid + 1] : 0;   // sum of chunks strictly above mine
    int best = 0;
    for (int k = 7; k >= 0; k--) {
        acc += binv[k];
        if (acc >= NPRE) { best = base + k; break; }
    }
    red[tid] = best;
    __syncthreads();
    for (int off = 128; off > 0; off >>= 1) {
        if (tid < off) red[tid] = max(red[tid], red[tid + off]);
        __syncthreads();
    }
    if (tid == 0) g_thr[b] = red[0];
}

// Collect candidates above threshold, full-grid, packed composite keys
__global__ void k_collect() {
    int b = blockIdx.y;
    unsigned t = (unsigned)g_thr[b];
    int j4 = blockIdx.x * blockDim.x + threadIdx.x;
    if (j4 >= NT4) return;
    float4 v = ((const float4*)g_score[b])[j4];
    int j = j4 * 4;
    float vv[4] = {v.x, v.y, v.z, v.w};
    #pragma unroll
    for (int k = 0; k < 4; k++) {
        unsigned fk = fkey(vv[k]);
        if ((fk >> 21) >= t) {
            int slot = atomicAdd(&g_cnt[b], 1);
            if (slot < CAP) {
                int jk = j + k;
                int a2 = jk / HW, s2 = jk - a2 * HW;
                unsigned i = (unsigned)(s2 * 6 + a2);   // original reshaped row index
                g_ck[b][slot] = ((unsigned long long)fk << 32) | (0xFFFFFFFFu - i);
            }
        }
    }
}

// Rank-sort candidates O(C^2), take top-100, decode boxes into scratch
__global__ void k_rankdecode(const float* __restrict__ cls,
                             const float* __restrict__ box,
                             const float* __restrict__ dir,
                             const float* __restrict__ anc) {
    int b = blockIdx.x, tid = threadIdx.x;  // 256 threads
    __shared__ unsigned long long ck[CAP];
    __shared__ int topi[NPRE];
    int C = min(g_cnt[b], CAP);
    for (int u = tid; u < C; u += 256) ck[u] = g_ck[b][u];
    __syncthreads();
    for (int u = tid; u < C; u += 256) {
        unsigned long long k = ck[u];
        int r = 0;
        for (int w = 0; w < C; w++) r += (ck[w] > k);
        if (r < NPRE) topi[r] = (int)(0xFFFFFFFFu - (unsigned)k);
    }
    __syncthreads();

    if (tid < NPRE) {
        const float PI = 3.14159265358979323846f;
        int i = topi[tid];
        int s = i / 6, a = i - 6 * s;

        const float* cb = cls + (size_t)b * 18 * HW + s;
        #pragma unroll
        for (int c = 0; c < 3; c++) {
            float x = cb[(size_t)(3 * a + c) * HW];
            g_sc3x[b][c][tid] = 0.5f * tanhf(0.5f * x) + 0.5f; // sigmoid
        }

        const float* pb = box + (size_t)b * 42 * HW + s;
        float d[7];
        #pragma unroll
        for (int j = 0; j < 7; j++) d[j] = pb[(size_t)(7 * a + j) * HW];

        const float* db = dir + (size_t)b * 12 * HW + s;
        float d0 = db[(size_t)(2 * a) * HW];
        float d1 = db[(size_t)(2 * a + 1) * HW];
        int dircls = (d1 > d0) ? 1 : 0;

        const float* ab = anc + (size_t)i * 7;
        float xa = ab[0], ya = ab[1], za = ab[2];
        float wa = ab[3], la = ab[4], ha = ab[5], ra = ab[6];

        float da = sqrtf(wa * wa + la * la);
        float x = d[0] * da + xa;
        float y = d[1] * da + ya;
        float z = d[2] * ha + za + ha * 0.5f;
        float w = wa * expf(d[3]);
        float l = la * expf(d[4]);
        float h = ha * expf(d[5]);
        z = z - h * 0.5f;
        float th0 = ra + d[6];
        float lp  = th0 - floorf(th0 / PI + 1.0f) * PI;
        float th  = lp + (1.0f - (float)dircls) * PI;

        g_bbx[b][tid][0] = x; g_bbx[b][tid][1] = y; g_bbx[b][tid][2] = z;
        g_bbx[b][tid][3] = w; g_bbx[b][tid][4] = l; g_bbx[b][tid][5] = h;
        g_bbx[b][tid][6] = th;

        float x1 = x - w * 0.5f, y1 = y - l * 0.5f;
        float x2 = x + w * 0.5f, y2 = y + l * 0.5f;
        g_b2dx[b][tid][0] = x1; g_b2dx[b][tid][1] = y1;
        g_b2dx[b][tid][2] = x2; g_b2dx[b][tid][3] = y2;
        g_areax[b][tid] = (x2 - x1) * (y2 - y1);
    }
}

// Per (batch, class): sort, parallel suppression bit-matrix, bitwise greedy sweep
__global__ void k_nms() {
    int c = blockIdx.x, b = blockIdx.y, tid = threadIdx.x;  // 128 threads

    __shared__ unsigned long long key[NPRE];
    __shared__ float kvs[NPRE];
    __shared__ int   ord[NPRE];
    __shared__ float sx1[NPRE], sy1[NPRE], sx2[NPRE], sy2[NPRE], sar[NPRE];
    __shared__ unsigned supw[NPRE][4];
    __shared__ unsigned km[4];

    if (tid < 4) km[tid] = 0;
    if (tid < NPRE) {
        float s = g_sc3x[b][c][tid];
        float kv = (s > 0.1f) ? s : -FLT_MAX;   // valid ? score : -inf key
        kvs[tid] = kv;
        key[tid] = ((unsigned long long)fkey(kv) << 32) | (0xFFFFFFFFu - (unsigned)tid);
    }
    __syncthreads();
    if (tid < NPRE) {   // stable descending rank (exact argsort semantics)
        unsigned long long k = key[tid];
        int r = 0;
        #pragma unroll 4
        for (int u = 0; u < NPRE; u++) r += (key[u] > k);
        ord[r] = tid;
    }
    __syncthreads();
    if (tid < NPRE) {   // gather boxes in sorted order, init keep bits = valid
        int p = ord[tid];
        sx1[tid] = g_b2dx[b][p][0]; sy1[tid] = g_b2dx[b][p][1];
        sx2[tid] = g_b2dx[b][p][2]; sy2[tid] = g_b2dx[b][p][3];
        sar[tid] = g_areax[b][p];
        if (kvs[p] != -FLT_MAX) atomicOr(&km[tid >> 5], 1u << (tid & 31));
    }
    __syncthreads();
    if (tid < NPRE) {   // suppression row ii=tid vs all jj>ii, in parallel
        float ax1 = sx1[tid], ay1 = sy1[tid], ax2 = sx2[tid], ay2 = sy2[tid];
        float aa = sar[tid];
        unsigned w0 = 0, w1 = 0, w2 = 0, w3 = 0;
        for (int jj = tid + 1; jj < NPRE; jj++) {
            float x1 = fmaxf(ax1, sx1[jj]);
            float y1 = fmaxf(ay1, sy1[jj]);
            float x2 = fminf(ax2, sx2[jj]);
            float y2 = fminf(ay2, sy2[jj]);
            float inter = fmaxf(x2 - x1, 0.0f) * fmaxf(y2 - y1, 0.0f);
            float iou = inter / (aa + sar[jj] - inter + 1e-8f);
            if (iou > 0.01f) {
                unsigned bit = 1u << (jj & 31);
                if (jj < 32) w0 |= bit; else if (jj < 64) w1 |= bit;
                else if (jj < 96) w2 |= bit; else w3 |= bit;
            }
        }
        supw[tid][0] = w0; supw[tid][1] = w1; supw[tid][2] = w2; supw[tid][3] = w3;
    }
    __syncthreads();
    if (tid == 0) {     // greedy sweep: 128-bit register AND-NOT, 100 iterations
        unsigned k0 = km[0], k1 = km[1], k2 = km[2], k3 = km[3];
        for (int ii = 0; ii < NPRE; ii++) {
            unsigned bit;
            if (ii < 32) bit = (k0 >> ii) & 1u;
            else if (ii < 64) bit = (k1 >> (ii - 32)) & 1u;
            else if (ii < 96) bit = (k2 >> (ii - 64)) & 1u;
            else bit = (k3 >> (ii - 96)) & 1u;
            if (bit) {
                k0 &= ~supw[ii][0]; k1 &= ~supw[ii][1];
                k2 &= ~supw[ii][2]; k3 &= ~supw[ii][3];
            }
        }
        km[0] = k0; km[1] = k1; km[2] = k2; km[3] = k3;
    }
    __syncthreads();
    if (tid < NPRE) {   // fv[p] = keep ? score : -1  (keep already includes valid)
        int p = ord[tid];
        unsigned bit = (km[tid >> 5] >> (tid & 31)) & 1u;
        g_fv[b][c * NPRE + p] = bit ? g_sc3x[b][c][p] : -1.0f;
    }
}

// Final top-50 over 300 flat entries, (value desc, flat index asc) — exact top_k
__global__ void k_out(float* __restrict__ out) {
    int b = blockIdx.x, tid = threadIdx.x;  // 320 threads, 300 active
    __shared__ unsigned long long key[3 * NPRE];
    __shared__ float fvs[3 * NPRE];
    if (tid < 3 * NPRE) {
        float v = g_fv[b][tid];
        fvs[tid] = v;
        key[tid] = ((unsigned long long)fkey(v) << 32) | (0xFFFFFFFFu - (unsigned)tid);
    }
    __syncthreads();
    if (tid < 3 * NPRE) {
        unsigned long long k = key[tid];
        int r = 0;
        #pragma unroll 4
        for (int u = 0; u < 3 * NPRE; u++) r += (key[u] > k);
        if (r < MAXN) {
            int sel = tid % NPRE;
            int lab = tid / NPRE;
            float v = fvs[tid];
            float* ob = out + (size_t)b * MAXN * 7 + (size_t)r * 7;
            #pragma unroll
            for (int j = 0; j < 7; j++) ob[j] = g_bbx[b][sel][j];
            out[BSZ * MAXN * 7 +                  b * MAXN + r] = (float)lab;
            out[BSZ * MAXN * 7 + BSZ * MAXN +     b * MAXN + r] = v;
            out[BSZ * MAXN * 7 + 2 * BSZ * MAXN + b * MAXN + r] = (v > 0.0f) ? 1.0f : 0.0f;
        }
    }
}

// ---------------------------------------------------------------------------
extern "C" void kernel_launch(void* const* d_in, const int* in_sizes, int n_in,
                              void* d_out, int out_size) {
    const float* cls = (const float*)d_in[0]; // (16,18,248,216)
    const float* box = (const float*)d_in[1]; // (16,42,248,216)
    const float* dir = (const float*)d_in[2]; // (16,12,248,216)
    const float* anc = (const float*)d_in[3]; // (248,216,3,2,7)
    float* out = (float*)d_out;

    k_zero<<<(BSZ * NBINS + 255) / 256, 256>>>();

    dim3 g1((NT4 + 255) / 256, BSZ);
    k_score<<<g1, 256>>>(cls);

    k_thresh<<<BSZ, 256>>>();

    k_collect<<<g1, 256>>>();

    k_rankdecode<<<BSZ, 256>>>(cls, box, dir, anc);

    dim3 g2(3, BSZ);
    k_nms<<<g2, 128>>>();

    k_out<<<BSZ, 320>>>(out);
}